// round 1
// baseline (speedup 1.0000x reference)
#include <cuda_runtime.h>

// Problem constants (fixed shapes for this problem instance)
#define QB   16      // queries per block
#define NT   256     // threads per block
#define HH   32      // neighbors per query
#define KK   15      // kernel points
#define KPAD 16      // padded K for float4 smem rows
#define CC   64      // Cin
#define DD   64      // Cout
#define KC   (KK*CC) // 960
#define KP_INV (1.0f/1.2f)

// smem: w[QB][HH][16] + weighted[QB][960] + inds[QB][HH] + q[QB*3] + kp[48] + ncnt[QB]
#define SMEM_FLOATS (QB*HH*KPAD + QB*KC)
#define SMEM_BYTES  (SMEM_FLOATS*4 + QB*HH*4 + (QB*3 + 48 + QB)*4)

// scratch: validity flag per support point (allocation-free __device__ global)
__device__ float g_valid[262144];

// ---------------------------------------------------------------------------
// Kernel 0: per-support-point validity flag: (sum_c x[m,:] > 0) ? 1 : 0
// One warp per row, fully coalesced.
// ---------------------------------------------------------------------------
__global__ void valid_kernel(const float* __restrict__ x, int M) {
    int row  = blockIdx.x * 8 + (threadIdx.x >> 5);
    int lane = threadIdx.x & 31;
    if (row >= M) return;
    float s = x[row * CC + lane] + x[row * CC + 32 + lane];
    #pragma unroll
    for (int off = 16; off > 0; off >>= 1)
        s += __shfl_xor_sync(0xffffffffu, s, off);
    if (lane == 0) g_valid[row] = (s > 0.0f) ? 1.0f : 0.0f;
}

// ---------------------------------------------------------------------------
// Fused KPConv kernel. One block = QB queries, 256 threads.
//   thread -> (c = tid&63, qs = tid>>6); each thread owns 4 queries.
// ---------------------------------------------------------------------------
extern __shared__ float smem[];

__global__ __launch_bounds__(NT) void kpconv_kernel(
    const float* __restrict__ q_pts,        // [N,3]
    const float* __restrict__ s_pts,        // [M,3]
    const int*   __restrict__ neighb_inds,  // [N,HH]
    const float* __restrict__ x,            // [M,CC]
    const float* __restrict__ kernel_points,// [KK,3]
    const float* __restrict__ weights,      // [KK,CC,DD] == [960][64]
    float*       __restrict__ out,          // [N,DD]
    int N)
{
    float* s_w        = smem;                                  // QB*HH*16
    float* s_weighted = smem + QB*HH*KPAD;                     // QB*960
    int*   s_inds     = (int*)(s_weighted + QB*KC);            // QB*HH
    float* s_q        = (float*)(s_inds + QB*HH);              // QB*3
    float* s_kp       = s_q + QB*3;                            // 48
    float* s_ncnt     = s_kp + 48;                             // QB

    const int tid   = threadIdx.x;
    const int qbase = blockIdx.x * QB;

    // --- load query points, kernel points, init counters ---
    if (tid < QB*3) {
        int q = tid / 3, p = tid % 3;
        int gq = qbase + q; if (gq >= N) gq = N - 1;
        s_q[tid] = q_pts[gq*3 + p];
    }
    if (tid >= 64 && tid < 64 + KK*3) s_kp[tid - 64] = kernel_points[tid - 64];
    if (tid >= 128 && tid < 128 + QB) s_ncnt[tid - 128] = 0.0f;
    __syncthreads();

    // --- phase 0: influence weights w[q][h][k], neighbor inds, valid counts ---
    for (int p = tid; p < QB*HH; p += NT) {
        int q = p >> 5, h = p & 31;
        int gq = qbase + q; if (gq >= N) gq = N - 1;
        int ind = neighb_inds[gq*HH + h];
        s_inds[p] = ind;
        atomicAdd(&s_ncnt[q], g_valid[ind]);
        float nx = s_pts[ind*3 + 0] - s_q[q*3 + 0];
        float ny = s_pts[ind*3 + 1] - s_q[q*3 + 1];
        float nz = s_pts[ind*3 + 2] - s_q[q*3 + 2];
        float wl[KPAD];
        #pragma unroll
        for (int k = 0; k < KK; k++) {
            float dx = nx - s_kp[k*3 + 0];
            float dy = ny - s_kp[k*3 + 1];
            float dz = nz - s_kp[k*3 + 2];
            float d2 = dx*dx + dy*dy + dz*dz;
            wl[k] = fmaxf(1.0f - sqrtf(d2) * KP_INV, 0.0f);
        }
        wl[15] = 0.0f;
        // float4 stores: avoid 16-way bank conflicts of the 64B-stride layout
        float4* wrow = (float4*)(s_w + p * KPAD);
        wrow[0] = make_float4(wl[0],  wl[1],  wl[2],  wl[3]);
        wrow[1] = make_float4(wl[4],  wl[5],  wl[6],  wl[7]);
        wrow[2] = make_float4(wl[8],  wl[9],  wl[10], wl[11]);
        wrow[3] = make_float4(wl[12], wl[13], wl[14], wl[15]);
    }
    __syncthreads();

    // --- stage A: weighted[q][k][c] = sum_h w[q][h][k] * x[ind[q][h]][c] ---
    const int c  = tid & 63;
    const int qs = tid >> 6;     // 0..3, owns queries qs*4 .. qs*4+3

    float acc[4][KK];
    #pragma unroll
    for (int iq = 0; iq < 4; iq++)
        #pragma unroll
        for (int k = 0; k < KK; k++) acc[iq][k] = 0.0f;

    #pragma unroll 2
    for (int h = 0; h < HH; h++) {
        #pragma unroll
        for (int iq = 0; iq < 4; iq++) {
            const int q   = qs*4 + iq;
            const int ind = s_inds[q*HH + h];
            const float fv = __ldg(&x[ind*CC + c]);
            const float4* wp = (const float4*)(s_w + (q*HH + h)*KPAD);
            const float4 w0 = wp[0], w1 = wp[1], w2 = wp[2], w3 = wp[3];
            acc[iq][0]  += w0.x*fv;  acc[iq][1]  += w0.y*fv;
            acc[iq][2]  += w0.z*fv;  acc[iq][3]  += w0.w*fv;
            acc[iq][4]  += w1.x*fv;  acc[iq][5]  += w1.y*fv;
            acc[iq][6]  += w1.z*fv;  acc[iq][7]  += w1.w*fv;
            acc[iq][8]  += w2.x*fv;  acc[iq][9]  += w2.y*fv;
            acc[iq][10] += w2.z*fv;  acc[iq][11] += w2.w*fv;
            acc[iq][12] += w3.x*fv;  acc[iq][13] += w3.y*fv;
            acc[iq][14] += w3.z*fv;
        }
    }
    #pragma unroll
    for (int iq = 0; iq < 4; iq++) {
        const int q = qs*4 + iq;
        #pragma unroll
        for (int k = 0; k < KK; k++)
            s_weighted[q*KC + k*CC + c] = acc[iq][k];   // coalesced, conflict-free
    }
    __syncthreads();

    // --- stage B: out[q][d] = sum_kc weighted[q][kc] * W[kc][d] ---
    const int d = c;
    float o[4] = {0.f, 0.f, 0.f, 0.f};
    #pragma unroll 4
    for (int kc = 0; kc < KC; kc += 4) {
        const float wa = __ldg(&weights[(kc+0)*DD + d]);
        const float wb = __ldg(&weights[(kc+1)*DD + d]);
        const float wc = __ldg(&weights[(kc+2)*DD + d]);
        const float wd = __ldg(&weights[(kc+3)*DD + d]);
        #pragma unroll
        for (int iq = 0; iq < 4; iq++) {
            const float4 v = *(const float4*)(s_weighted + (qs*4 + iq)*KC + kc);
            o[iq] += v.x*wa + v.y*wb + v.z*wc + v.w*wd;
        }
    }

    #pragma unroll
    for (int iq = 0; iq < 4; iq++) {
        const int q  = qs*4 + iq;
        const int gq = qbase + q;
        if (gq < N) {
            const float cnt = fmaxf(s_ncnt[q], 1.0f);
            out[gq*DD + d] = o[iq] / cnt;
        }
    }
}

// ---------------------------------------------------------------------------
extern "C" void kernel_launch(void* const* d_in, const int* in_sizes, int n_in,
                              void* d_out, int out_size) {
    const float* q_pts         = (const float*)d_in[0];
    const float* s_pts         = (const float*)d_in[1];
    const int*   neighb_inds   = (const int*)  d_in[2];
    const float* x             = (const float*)d_in[3];
    const float* kernel_points = (const float*)d_in[4];
    const float* weights       = (const float*)d_in[5];
    float*       out           = (float*)d_out;

    const int N = in_sizes[0] / 3;
    const int M = in_sizes[1] / 3;

    cudaFuncSetAttribute(kpconv_kernel,
                         cudaFuncAttributeMaxDynamicSharedMemorySize, SMEM_BYTES);

    valid_kernel<<<(M + 7) / 8, 256>>>(x, M);
    kpconv_kernel<<<(N + QB - 1) / QB, NT, SMEM_BYTES>>>(
        q_pts, s_pts, neighb_inds, x, kernel_points, weights, out, N);
}

// round 6
// speedup vs baseline: 2.0912x; 2.0912x over previous
#include <cuda_runtime.h>

// Fixed problem shape
#define QB   16      // queries per block
#define NT   256     // threads per block
#define HH   32      // neighbors per query
#define KK   15      // kernel points
#define KPAD 16      // padded K for float4 smem rows
#define CC   64      // Cin
#define DD   64      // Cout
#define KC   960     // KK*CC
#define KP_INV (1.0f/1.2f)

// smem layout (floats):
//   s_w        [0, 8192)        QB*HH*KPAD   (reused as s_red in stage B)
//   s_weighted [8192, 23552)    QB*KC
//   s_inds     512 ints
//   s_q        48, s_kp 48, s_ncnt 16
#define OFF_WGT   8192
#define OFF_INDS  23552
#define SMEM_BYTES ((23552 + 512 + 48 + 48 + 16) * 4)

__device__ float g_valid[65536];   // validity flag per support point (M <= 65536)

// ---------------------------------------------------------------------------
// Kernel 0: g_valid[m] = (sum_c x[m,c] > 0) ? 1 : 0. One warp per row.
// ---------------------------------------------------------------------------
__global__ void valid_kernel(const float* __restrict__ x, int M) {
    int row  = blockIdx.x * 8 + (threadIdx.x >> 5);
    int lane = threadIdx.x & 31;
    if (row >= M) return;
    float s = x[row * CC + lane] + x[row * CC + 32 + lane];
    #pragma unroll
    for (int off = 16; off > 0; off >>= 1)
        s += __shfl_xor_sync(0xffffffffu, s, off);
    if (lane == 0) g_valid[row] = (s > 0.0f) ? 1.0f : 0.0f;
}

// ---------------------------------------------------------------------------
// Fused KPConv: one block = 16 queries, 256 threads, 2 blocks/SM.
// ---------------------------------------------------------------------------
extern __shared__ float smem[];

__global__ __launch_bounds__(NT, 2) void kpconv_kernel(
    const float* __restrict__ q_pts,         // [N,3]
    const float* __restrict__ s_pts,         // [M,3]
    const int*   __restrict__ neighb_inds,   // [N,HH]
    const float* __restrict__ x,             // [M,CC]
    const float* __restrict__ kernel_points, // [KK,3]
    const float* __restrict__ weights,       // [KC,DD]
    float*       __restrict__ out,           // [N,DD]
    int N)
{
    float* s_w        = smem;                      // QB*HH*KPAD
    float* s_weighted = smem + OFF_WGT;            // QB*KC
    int*   s_inds     = (int*)(smem + OFF_INDS);   // QB*HH
    float* s_q        = smem + OFF_INDS + 512;     // QB*3
    float* s_kp       = s_q + 48;                  // KK*3
    float* s_ncnt     = s_kp + 48;                 // QB

    const int tid   = threadIdx.x;
    const int qbase = blockIdx.x * QB;

    // --- header loads ---
    if (tid < QB*3) {
        int q = tid / 3, p = tid % 3;
        int gq = qbase + q; if (gq >= N) gq = N - 1;
        s_q[tid] = q_pts[gq*3 + p];
    }
    if (tid >= 64 && tid < 64 + KK*3) s_kp[tid - 64] = kernel_points[tid - 64];
    __syncthreads();

    // --- phase 0: influence weights + inds + valid counts (warp reduce) ---
    const int lane = tid & 31;
    #pragma unroll
    for (int pass = 0; pass < 2; pass++) {
        int p = tid + pass * NT;          // p = q*32 + h, warp-uniform q
        int q = p >> 5, h = p & 31;
        int gq = qbase + q; if (gq >= N) gq = N - 1;
        int ind = neighb_inds[gq*HH + h];
        s_inds[p] = ind;
        float v = g_valid[ind];
        #pragma unroll
        for (int off = 16; off > 0; off >>= 1)
            v += __shfl_xor_sync(0xffffffffu, v, off);
        if (lane == 0) s_ncnt[q] = v;
        float nx = s_pts[ind*3 + 0] - s_q[q*3 + 0];
        float ny = s_pts[ind*3 + 1] - s_q[q*3 + 1];
        float nz = s_pts[ind*3 + 2] - s_q[q*3 + 2];
        float wl[KPAD];
        #pragma unroll
        for (int k = 0; k < KK; k++) {
            float dx = nx - s_kp[k*3 + 0];
            float dy = ny - s_kp[k*3 + 1];
            float dz = nz - s_kp[k*3 + 2];
            wl[k] = fmaxf(1.0f - sqrtf(dx*dx + dy*dy + dz*dz) * KP_INV, 0.0f);
        }
        wl[15] = 0.0f;
        float4* wrow = (float4*)(s_w + p * KPAD);
        wrow[0] = make_float4(wl[0],  wl[1],  wl[2],  wl[3]);
        wrow[1] = make_float4(wl[4],  wl[5],  wl[6],  wl[7]);
        wrow[2] = make_float4(wl[8],  wl[9],  wl[10], wl[11]);
        wrow[3] = make_float4(wl[12], wl[13], wl[14], wl[15]);
    }
    __syncthreads();

    // --- stage A: thread owns channels (c0, c0+32) and queries (2qg, 2qg+1) ---
    {
        const int c0 = lane;
        const int c1 = lane + 32;
        const int qg = tid >> 5;               // 0..7

        float acc[2][2][KK];
        #pragma unroll
        for (int qi = 0; qi < 2; qi++)
            #pragma unroll
            for (int ci = 0; ci < 2; ci++)
                #pragma unroll
                for (int k = 0; k < KK; k++) acc[qi][ci][k] = 0.0f;

        #pragma unroll 4
        for (int h = 0; h < HH; h++) {
            #pragma unroll
            for (int qi = 0; qi < 2; qi++) {
                const int q   = qg*2 + qi;
                const int ind = s_inds[q*HH + h];
                const float fa = __ldg(x + ind*CC + c0);
                const float fb = __ldg(x + ind*CC + c1);
                const float4* wp = (const float4*)(s_w + (q*HH + h)*KPAD);
                const float4 w0 = wp[0], w1 = wp[1], w2 = wp[2], w3 = wp[3];
                acc[qi][0][0]  += w0.x*fa;  acc[qi][1][0]  += w0.x*fb;
                acc[qi][0][1]  += w0.y*fa;  acc[qi][1][1]  += w0.y*fb;
                acc[qi][0][2]  += w0.z*fa;  acc[qi][1][2]  += w0.z*fb;
                acc[qi][0][3]  += w0.w*fa;  acc[qi][1][3]  += w0.w*fb;
                acc[qi][0][4]  += w1.x*fa;  acc[qi][1][4]  += w1.x*fb;
                acc[qi][0][5]  += w1.y*fa;  acc[qi][1][5]  += w1.y*fb;
                acc[qi][0][6]  += w1.z*fa;  acc[qi][1][6]  += w1.z*fb;
                acc[qi][0][7]  += w1.w*fa;  acc[qi][1][7]  += w1.w*fb;
                acc[qi][0][8]  += w2.x*fa;  acc[qi][1][8]  += w2.x*fb;
                acc[qi][0][9]  += w2.y*fa;  acc[qi][1][9]  += w2.y*fb;
                acc[qi][0][10] += w2.z*fa;  acc[qi][1][10] += w2.z*fb;
                acc[qi][0][11] += w2.w*fa;  acc[qi][1][11] += w2.w*fb;
                acc[qi][0][12] += w3.x*fa;  acc[qi][1][12] += w3.x*fb;
                acc[qi][0][13] += w3.y*fa;  acc[qi][1][13] += w3.y*fb;
                acc[qi][0][14] += w3.z*fa;  acc[qi][1][14] += w3.z*fb;
            }
        }
        #pragma unroll
        for (int qi = 0; qi < 2; qi++) {
            const int q = qg*2 + qi;
            #pragma unroll
            for (int k = 0; k < KK; k++) {
                s_weighted[q*KC + k*CC + c0] = acc[qi][0][k];
                s_weighted[q*KC + k*CC + c1] = acc[qi][1][k];
            }
        }
    }
    __syncthreads();

    // --- stage B: register-blocked GEMM [16 x 960] @ [960 x 64] ---
    // thread = (d4 = tid&15 -> 4 d's, q4 = (tid>>4)&3 -> 4 q's, seg = tid>>6 -> kc quarter)
    {
        const int d4  = tid & 15;
        const int q4  = (tid >> 4) & 3;
        const int seg = tid >> 6;
        const int kc0 = seg * 240;

        float4 o0 = make_float4(0.f,0.f,0.f,0.f);
        float4 o1 = o0, o2 = o0, o3 = o0;

        const float4* Wb = (const float4*)weights + d4;   // + kc*16 per row

        #pragma unroll 2
        for (int it = 0; it < 60; it++) {
            const int kc = kc0 + it*4;
            const float4 wa = __ldg(Wb + (kc+0)*16);
            const float4 wb = __ldg(Wb + (kc+1)*16);
            const float4 wc = __ldg(Wb + (kc+2)*16);
            const float4 wd = __ldg(Wb + (kc+3)*16);
            const float4 v0 = *(const float4*)(s_weighted + (q4*4+0)*KC + kc);
            const float4 v1 = *(const float4*)(s_weighted + (q4*4+1)*KC + kc);
            const float4 v2 = *(const float4*)(s_weighted + (q4*4+2)*KC + kc);
            const float4 v3 = *(const float4*)(s_weighted + (q4*4+3)*KC + kc);
            #define UPD(o, v) \
                o.x += v.x*wa.x; o.y += v.x*wa.y; o.z += v.x*wa.z; o.w += v.x*wa.w; \
                o.x += v.y*wb.x; o.y += v.y*wb.y; o.z += v.y*wb.z; o.w += v.y*wb.w; \
                o.x += v.z*wc.x; o.y += v.z*wc.y; o.z += v.z*wc.z; o.w += v.z*wc.w; \
                o.x += v.w*wd.x; o.y += v.w*wd.y; o.z += v.w*wd.z; o.w += v.w*wd.w;
            UPD(o0, v0) UPD(o1, v1) UPD(o2, v2) UPD(o3, v3)
            #undef UPD
        }

        // partials per kc-quarter -> smem (reuse s_w region; all s_w reads done)
        float* s_red = smem;   // [seg][q*64+d] : 4 * 1024 floats
        *(float4*)(s_red + seg*1024 + (q4*4+0)*DD + d4*4) = o0;
        *(float4*)(s_red + seg*1024 + (q4*4+1)*DD + d4*4) = o1;
        *(float4*)(s_red + seg*1024 + (q4*4+2)*DD + d4*4) = o2;
        *(float4*)(s_red + seg*1024 + (q4*4+3)*DD + d4*4) = o3;
    }
    __syncthreads();

    // --- final reduce over 4 segments + normalize + store ---
    {
        const float* s_red = smem;
        const int o = tid * 4;                 // output element base (q*64 + d)
        float4 r0 = *(const float4*)(s_red + 0*1024 + o);
        float4 r1 = *(const float4*)(s_red + 1*1024 + o);
        float4 r2 = *(const float4*)(s_red + 2*1024 + o);
        float4 r3 = *(const float4*)(s_red + 3*1024 + o);
        const int q  = tid >> 4;
        const int gq = qbase + q;
        const float cnt = fmaxf(s_ncnt[q], 1.0f);
        const float inv = 1.0f / cnt;
        float4 r;
        r.x = (r0.x + r1.x + r2.x + r3.x) * inv;
        r.y = (r0.y + r1.y + r2.y + r3.y) * inv;
        r.z = (r0.z + r1.z + r2.z + r3.z) * inv;
        r.w = (r0.w + r1.w + r2.w + r3.w) * inv;
        if (gq < N)
            *(float4*)(out + gq*DD + (tid & 15)*4) = r;
    }
}

// ---------------------------------------------------------------------------
extern "C" void kernel_launch(void* const* d_in, const int* in_sizes, int n_in,
                              void* d_out, int out_size) {
    const float* q_pts         = (const float*)d_in[0];
    const float* s_pts         = (const float*)d_in[1];
    const int*   neighb_inds   = (const int*)  d_in[2];
    const float* x             = (const float*)d_in[3];
    const float* kernel_points = (const float*)d_in[4];
    const float* weights       = (const float*)d_in[5];
    float*       out           = (float*)d_out;

    const int N = in_sizes[0] / 3;
    const int M = in_sizes[1] / 3;

    cudaFuncSetAttribute(kpconv_kernel,
                         cudaFuncAttributeMaxDynamicSharedMemorySize, SMEM_BYTES);

    valid_kernel<<<(M + 7) / 8, 256>>>(x, M);
    kpconv_kernel<<<(N + QB - 1) / QB, NT, SMEM_BYTES>>>(
        q_pts, s_pts, neighb_inds, x, kernel_points, weights, out, N);
}

// round 8
// speedup vs baseline: 2.4420x; 1.1677x over previous
#include <cuda_runtime.h>

// Fixed problem shape
#define QB   16      // queries per block
#define NT   256     // threads per block
#define HH   32      // neighbors per query
#define KK   15      // kernel points
#define KPAD 16      // padded K
#define CC   64      // Cin
#define DD   64      // Cout
#define KC   960     // KK*CC
#define KP_INV (1.0f/1.2f)

// smem layout (floats):
//   s_w        [0, 8192)      QB*HH*KPAD  (reused as s_red: 8 segs x 1024)
//   s_weighted [8192, 23552)  QB*KC
//   s_inds, s_q, s_kp, s_ncnt after
#define OFF_WGT   8192
#define OFF_INDS  23552
#define SMEM_BYTES ((23552 + 512 + 48 + 48 + 16) * 4)

// packed support-point table: (x, y, z, valid_flag)
__device__ float4 g_spts4[65536];

union F2U { unsigned long long u; float2 f; };

__device__ __forceinline__ void fma2(unsigned long long& acc,
                                     unsigned long long a,
                                     unsigned long long b) {
    asm("fma.rn.f32x2 %0, %1, %2, %0;" : "+l"(acc) : "l"(a), "l"(b));
}
__device__ __forceinline__ unsigned long long dup2(float v) {
    unsigned long long d;
    asm("mov.b64 %0, {%1, %1};" : "=l"(d) : "r"(__float_as_uint(v)));
    return d;
}

// ---------------------------------------------------------------------------
// Prologue: g_spts4[m] = (s_pts[m].xyz, rowsum(x[m]) > 0 ? 1 : 0)
// ---------------------------------------------------------------------------
__global__ void prep_kernel(const float* __restrict__ x,
                            const float* __restrict__ s_pts, int M) {
    int row  = blockIdx.x * 8 + (threadIdx.x >> 5);
    int lane = threadIdx.x & 31;
    if (row >= M) return;
    float s = x[row * CC + lane] + x[row * CC + 32 + lane];
    #pragma unroll
    for (int off = 16; off > 0; off >>= 1)
        s += __shfl_xor_sync(0xffffffffu, s, off);
    if (lane == 0) {
        float4 v;
        v.x = s_pts[3*row + 0];
        v.y = s_pts[3*row + 1];
        v.z = s_pts[3*row + 2];
        v.w = (s > 0.0f) ? 1.0f : 0.0f;
        g_spts4[row] = v;
    }
}

// ---------------------------------------------------------------------------
// Fused KPConv: one block = 16 queries, 256 threads, 2 blocks/SM.
// ---------------------------------------------------------------------------
extern __shared__ float smem[];

__global__ __launch_bounds__(NT, 2) void kpconv_kernel(
    const float* __restrict__ q_pts,         // [N,3]
    const int*   __restrict__ neighb_inds,   // [N,HH]
    const float* __restrict__ x,             // [M,CC]
    const float* __restrict__ kernel_points, // [KK,3]
    const float* __restrict__ weights,       // [KC,DD]
    float*       __restrict__ out,           // [N,DD]
    int N)
{
    float* s_w        = smem;                      // QB*HH*KPAD (-> s_red)
    float* s_weighted = smem + OFF_WGT;            // QB*KC
    int*   s_inds     = (int*)(smem + OFF_INDS);   // QB*HH
    float* s_q        = smem + OFF_INDS + 512;     // QB*3
    float* s_kp       = s_q + 48;                  // KK*3
    float* s_ncnt     = s_kp + 48;                 // QB

    const int tid   = threadIdx.x;
    const int lane  = tid & 31;
    const int qbase = blockIdx.x * QB;

    // --- header loads ---
    if (tid < QB*3) {
        int q = tid / 3, p = tid % 3;
        int gq = qbase + q; if (gq >= N) gq = N - 1;
        s_q[tid] = q_pts[gq*3 + p];
    }
    if (tid >= 64 && tid < 64 + KK*3) s_kp[tid - 64] = kernel_points[tid - 64];
    __syncthreads();

    // --- phase 0: influence weights + inds + valid counts ---
    #pragma unroll
    for (int pass = 0; pass < 2; pass++) {
        int p = tid + pass * NT;          // p = q*32 + h (warp-uniform q)
        int q = p >> 5, h = p & 31;
        int gq = qbase + q; if (gq >= N) gq = N - 1;
        int ind = neighb_inds[gq*HH + h];
        s_inds[p] = ind;
        float4 sp = __ldg(&g_spts4[ind]);
        float v = sp.w;
        #pragma unroll
        for (int off = 16; off > 0; off >>= 1)
            v += __shfl_xor_sync(0xffffffffu, v, off);
        if (lane == 0) s_ncnt[q] = v;
        float nx = sp.x - s_q[q*3 + 0];
        float ny = sp.y - s_q[q*3 + 1];
        float nz = sp.z - s_q[q*3 + 2];
        float wl[KPAD];
        #pragma unroll
        for (int k = 0; k < KK; k++) {
            float dx = nx - s_kp[k*3 + 0];
            float dy = ny - s_kp[k*3 + 1];
            float dz = nz - s_kp[k*3 + 2];
            wl[k] = fmaxf(1.0f - sqrtf(dx*dx + dy*dy + dz*dz) * KP_INV, 0.0f);
        }
        wl[15] = 0.0f;
        float4* wrow = (float4*)(s_w + p * KPAD);
        wrow[0] = make_float4(wl[0],  wl[1],  wl[2],  wl[3]);
        wrow[1] = make_float4(wl[4],  wl[5],  wl[6],  wl[7]);
        wrow[2] = make_float4(wl[8],  wl[9],  wl[10], wl[11]);
        wrow[3] = make_float4(wl[12], wl[13], wl[14], wl[15]);
    }
    __syncthreads();

    // --- stage A (FFMA2, k-pair packed): thread owns channels (2*lane, 2*lane+1)
    //     and queries (2*qg, 2*qg+1). acc pair kp = (k=2kp, k=2kp+1). ---
    {
        const int cb = 2 * lane;
        const int qg = tid >> 5;

        unsigned long long acc[2][2][8];
        #pragma unroll
        for (int qi = 0; qi < 2; qi++)
            #pragma unroll
            for (int ci = 0; ci < 2; ci++)
                #pragma unroll
                for (int kp = 0; kp < 8; kp++) acc[qi][ci][kp] = 0ull;

        #pragma unroll 2
        for (int h = 0; h < HH; h++) {
            #pragma unroll
            for (int qi = 0; qi < 2; qi++) {
                const int q   = qg*2 + qi;
                const int ind = s_inds[q*HH + h];
                const float2 f = __ldg((const float2*)(x + ind*CC) + lane);
                const unsigned long long fda = dup2(f.x);
                const unsigned long long fdb = dup2(f.y);
                const ulonglong2* wp = (const ulonglong2*)(s_w + (q*HH + h)*KPAD);
                const ulonglong2 wA = wp[0], wB = wp[1], wC = wp[2], wD = wp[3];
                fma2(acc[qi][0][0], wA.x, fda);  fma2(acc[qi][1][0], wA.x, fdb);
                fma2(acc[qi][0][1], wA.y, fda);  fma2(acc[qi][1][1], wA.y, fdb);
                fma2(acc[qi][0][2], wB.x, fda);  fma2(acc[qi][1][2], wB.x, fdb);
                fma2(acc[qi][0][3], wB.y, fda);  fma2(acc[qi][1][3], wB.y, fdb);
                fma2(acc[qi][0][4], wC.x, fda);  fma2(acc[qi][1][4], wC.x, fdb);
                fma2(acc[qi][0][5], wC.y, fda);  fma2(acc[qi][1][5], wC.y, fdb);
                fma2(acc[qi][0][6], wD.x, fda);  fma2(acc[qi][1][6], wD.x, fdb);
                fma2(acc[qi][0][7], wD.y, fda);  fma2(acc[qi][1][7], wD.y, fdb);
            }
        }
        #pragma unroll
        for (int qi = 0; qi < 2; qi++) {
            const int q = qg*2 + qi;
            #pragma unroll
            for (int kp = 0; kp < 8; kp++) {
                F2U a0; a0.u = acc[qi][0][kp];
                F2U a1; a1.u = acc[qi][1][kp];
                *(float2*)(s_weighted + q*KC + (2*kp)*CC + cb) =
                    make_float2(a0.f.x, a1.f.x);
                if (kp < 7)
                    *(float2*)(s_weighted + q*KC + (2*kp+1)*CC + cb) =
                        make_float2(a0.f.y, a1.f.y);
            }
        }
    }
    __syncthreads();

    // --- stage B (FFMA2, d-pair packed): [16 x 960] @ [960 x 64].
    //     thread = (dg = tid&15 -> 4 d's, qg2 = (tid>>4)&1 -> 8 q's,
    //               seg = tid>>5 = warp -> 120-kc eighth). W read once/block. ---
    {
        const int dg  = tid & 15;
        const int qg2 = (tid >> 4) & 1;
        const int seg = tid >> 5;
        const int kc0 = seg * 120;

        unsigned long long o[8][2];
        #pragma unroll
        for (int q = 0; q < 8; q++) { o[q][0] = 0ull; o[q][1] = 0ull; }

        const ulonglong2* W2 = (const ulonglong2*)weights + dg;  // + kc*16/row

        for (int it = 0; it < 30; it++) {
            const int kc = kc0 + it*4;
            const ulonglong2 wk0 = __ldg(W2 + (kc+0)*16);
            const ulonglong2 wk1 = __ldg(W2 + (kc+1)*16);
            const ulonglong2 wk2 = __ldg(W2 + (kc+2)*16);
            const ulonglong2 wk3 = __ldg(W2 + (kc+3)*16);
            #pragma unroll
            for (int q = 0; q < 8; q++) {
                const int qq = qg2*8 + q;
                const float4 v = *(const float4*)(s_weighted + qq*KC + kc);
                unsigned long long vd;
                vd = dup2(v.x); fma2(o[q][0], wk0.x, vd); fma2(o[q][1], wk0.y, vd);
                vd = dup2(v.y); fma2(o[q][0], wk1.x, vd); fma2(o[q][1], wk1.y, vd);
                vd = dup2(v.z); fma2(o[q][0], wk2.x, vd); fma2(o[q][1], wk2.y, vd);
                vd = dup2(v.w); fma2(o[q][0], wk3.x, vd); fma2(o[q][1], wk3.y, vd);
            }
        }

        // partials per kc-eighth -> smem (reuse s_w region: 8 * 1024 floats)
        float* s_red = smem;
        #pragma unroll
        for (int q = 0; q < 8; q++) {
            const int qq = qg2*8 + q;
            F2U a0; a0.u = o[q][0];
            F2U a1; a1.u = o[q][1];
            *(float4*)(s_red + seg*1024 + qq*DD + dg*4) =
                make_float4(a0.f.x, a0.f.y, a1.f.x, a1.f.y);
        }
    }
    __syncthreads();

    // --- final reduce over 8 segments + normalize + store ---
    {
        const float* s_red = smem;
        const int o = tid * 4;                 // output element base (q*64 + d)
        float rx = 0.f, ry = 0.f, rz = 0.f, rw = 0.f;
        #pragma unroll
        for (int s = 0; s < 8; s++) {
            float4 r = *(const float4*)(s_red + s*1024 + o);
            rx += r.x; ry += r.y; rz += r.z; rw += r.w;
        }
        const int q  = tid >> 4;
        const int gq = qbase + q;
        const float inv = 1.0f / fmaxf(s_ncnt[q], 1.0f);
        if (gq < N)
            *(float4*)(out + gq*DD + (tid & 15)*4) =
                make_float4(rx*inv, ry*inv, rz*inv, rw*inv);
    }
}

// ---------------------------------------------------------------------------
extern "C" void kernel_launch(void* const* d_in, const int* in_sizes, int n_in,
                              void* d_out, int out_size) {
    const float* q_pts         = (const float*)d_in[0];
    const float* s_pts         = (const float*)d_in[1];
    const int*   neighb_inds   = (const int*)  d_in[2];
    const float* x             = (const float*)d_in[3];
    const float* kernel_points = (const float*)d_in[4];
    const float* weights       = (const float*)d_in[5];
    float*       out           = (float*)d_out;

    const int N = in_sizes[0] / 3;
    const int M = in_sizes[1] / 3;

    cudaFuncSetAttribute(kpconv_kernel,
                         cudaFuncAttributeMaxDynamicSharedMemorySize, SMEM_BYTES);

    prep_kernel<<<(M + 7) / 8, 256>>>(x, s_pts, M);
    kpconv_kernel<<<(N + QB - 1) / QB, NT, SMEM_BYTES>>>(
        q_pts, neighb_inds, x, kernel_points, weights, out, N);
}